// round 4
// baseline (speedup 1.0000x reference)
#include <cuda_runtime.h>
#include <cuda_bf16.h>

// Scratch (alloc-free rule: __device__ globals). N = 100000 <= MAXN.
#define MAXN (1 << 17)
__device__ float g_deg[MAXN];
__device__ float g_dinv[MAXN];
__device__ float g_a[MAXN];    // dinv[i]*x[i]   (layer-1 source values)
__device__ float g_S[MAXN];    // unnormalized layer-1 aggregate
__device__ float g_u[MAXN];    // dinv[i]*t[i]   (layer-2 source values)
__device__ float g_acc[MAXN];  // unnormalized layer-2 aggregate

#define EPT 16   // edges per thread in edge kernels

// ---------------------------------------------------------------------------
// Node kernels (tiny, O(N))
// ---------------------------------------------------------------------------

__global__ void init_kernel(int n) {
    int i = blockIdx.x * blockDim.x + threadIdx.x;
    if (i < n) g_deg[i] = 1.0f;   // self loop
}

// dinv[i] = 1/sqrt(deg[i]); a[i] = dinv[i]*x[i]
__global__ void prep_kernel(const float* __restrict__ x, int n) {
    int i = blockIdx.x * blockDim.x + threadIdx.x;
    if (i < n) {
        float di = 1.0f / sqrtf(g_deg[i]);   // deg >= 1 always (self loops)
        g_dinv[i] = di;
        g_a[i]    = di * __ldg(&x[i]);
    }
}

// s = dinv[i]*(S'[i] + a[i])  (the +a[i] is the self-loop edge)
// t[i] = sum_k relu(W1[k]*s + b1[k]) * W2[k];  u[i] = dinv[i]*t[i]
__global__ void t_kernel(const float* __restrict__ W1,
                         const float* __restrict__ b1,
                         const float* __restrict__ W2,
                         int n, int H) {
    int i = blockIdx.x * blockDim.x + threadIdx.x;
    if (i < n) {
        float di = g_dinv[i];
        float s  = di * (g_S[i] + g_a[i]);
        float acc = 0.0f;
        #pragma unroll 16
        for (int k = 0; k < H; k++) {
            float h = fmaf(__ldg(&W1[k]), s, __ldg(&b1[k]));
            h = fmaxf(h, 0.0f);
            acc = fmaf(h, __ldg(&W2[k]), acc);
        }
        g_u[i] = di * acc;
    }
}

// out[i] = dinv[i]*(acc[i] + u[i]) + b2   (the +u[i] is the self-loop edge)
__global__ void final_kernel(const float* __restrict__ b2,
                             float* __restrict__ out, int n) {
    int i = blockIdx.x * blockDim.x + threadIdx.x;
    if (i < n) {
        out[i] = g_dinv[i] * (g_acc[i] + g_u[i]) + __ldg(&b2[0]);
    }
}

// ---------------------------------------------------------------------------
// Edge kernels (int32 indices; EPT edges/thread via int4 loads).
// Per edge: at most 1 scattered gather + 1 scattered RED on L2-resident
// node arrays — the irreducible sector traffic for random indices.
// ---------------------------------------------------------------------------

// Also zeroes g_S (untouched by this kernel => no race).
__global__ void __launch_bounds__(256, 8)
deg_kernel(const int* __restrict__ col, int E, int N) {
    int i = blockIdx.x * blockDim.x + threadIdx.x;
    if (i < N) g_S[i] = 0.0f;

    int e = i * EPT;
    if (e + EPT - 1 < E) {
        int idx[EPT];
        #pragma unroll
        for (int v = 0; v < EPT / 4; v++) {
            int4 c = *reinterpret_cast<const int4*>(col + e + v * 4);
            idx[v * 4 + 0] = c.x; idx[v * 4 + 1] = c.y;
            idx[v * 4 + 2] = c.z; idx[v * 4 + 3] = c.w;
        }
        #pragma unroll
        for (int v = 0; v < EPT; v++) atomicAdd(&g_deg[idx[v]], 1.0f);
    } else {
        for (; e < E; e++) atomicAdd(&g_deg[col[e]], 1.0f);
    }
}

// S'[col] += a[row].  Also zeroes g_acc (untouched here => no race).
__global__ void __launch_bounds__(256, 8)
s_kernel(const int* __restrict__ row, const int* __restrict__ col,
         int E, int N) {
    int i = blockIdx.x * blockDim.x + threadIdx.x;
    if (i < N) g_acc[i] = 0.0f;

    int e = i * EPT;
    if (e + EPT - 1 < E) {
        int rs[EPT], cs[EPT];
        #pragma unroll
        for (int v = 0; v < EPT / 4; v++) {
            int4 r = *reinterpret_cast<const int4*>(row + e + v * 4);
            int4 c = *reinterpret_cast<const int4*>(col + e + v * 4);
            rs[v * 4 + 0] = r.x; rs[v * 4 + 1] = r.y;
            rs[v * 4 + 2] = r.z; rs[v * 4 + 3] = r.w;
            cs[v * 4 + 0] = c.x; cs[v * 4 + 1] = c.y;
            cs[v * 4 + 2] = c.z; cs[v * 4 + 3] = c.w;
        }
        float vals[EPT];
        #pragma unroll
        for (int v = 0; v < EPT; v++) vals[v] = __ldg(&g_a[rs[v]]);
        #pragma unroll
        for (int v = 0; v < EPT; v++) atomicAdd(&g_S[cs[v]], vals[v]);
    } else {
        for (; e < E; e++) atomicAdd(&g_S[col[e]], g_a[row[e]]);
    }
}

// acc[col] += u[row]
__global__ void __launch_bounds__(256, 8)
out_kernel(const int* __restrict__ row, const int* __restrict__ col, int E) {
    int i = blockIdx.x * blockDim.x + threadIdx.x;
    int e = i * EPT;
    if (e + EPT - 1 < E) {
        int rs[EPT], cs[EPT];
        #pragma unroll
        for (int v = 0; v < EPT / 4; v++) {
            int4 r = *reinterpret_cast<const int4*>(row + e + v * 4);
            int4 c = *reinterpret_cast<const int4*>(col + e + v * 4);
            rs[v * 4 + 0] = r.x; rs[v * 4 + 1] = r.y;
            rs[v * 4 + 2] = r.z; rs[v * 4 + 3] = r.w;
            cs[v * 4 + 0] = c.x; cs[v * 4 + 1] = c.y;
            cs[v * 4 + 2] = c.z; cs[v * 4 + 3] = c.w;
        }
        float vals[EPT];
        #pragma unroll
        for (int v = 0; v < EPT; v++) vals[v] = __ldg(&g_u[rs[v]]);
        #pragma unroll
        for (int v = 0; v < EPT; v++) atomicAdd(&g_acc[cs[v]], vals[v]);
    } else {
        for (; e < E; e++) atomicAdd(&g_acc[col[e]], g_u[row[e]]);
    }
}

// ---------------------------------------------------------------------------
// Launch
// ---------------------------------------------------------------------------

extern "C" void kernel_launch(void* const* d_in, const int* in_sizes, int n_in,
                              void* d_out, int out_size) {
    const float* x    = (const float*)d_in[0];
    const int*   eidx = (const int*)d_in[1];    // [2, E] int32
    const float* W1   = (const float*)d_in[2];
    const float* b1   = (const float*)d_in[3];
    const float* W2   = (const float*)d_in[4];
    const float* b2   = (const float*)d_in[5];
    float*       out  = (float*)d_out;

    int N = in_sizes[0];
    int E = in_sizes[1] / 2;
    int H = in_sizes[3];

    const int* row = eidx;
    const int* col = eidx + E;

    const int TB = 256;
    int nodeBlocks = (N + TB - 1) / TB;
    int edgeThreads = (E + EPT - 1) / EPT;
    // edge kernels also touch node range [0, N) for fused zeroing
    int edgeBlocks = (max(edgeThreads, N) + TB - 1) / TB;

    init_kernel<<<nodeBlocks, TB>>>(N);
    deg_kernel<<<edgeBlocks, TB>>>(col, E, N);
    prep_kernel<<<nodeBlocks, TB>>>(x, N);
    s_kernel<<<edgeBlocks, TB>>>(row, col, E, N);
    t_kernel<<<nodeBlocks, TB>>>(W1, b1, W2, N, H);
    out_kernel<<<edgeBlocks, TB>>>(row, col, E);
    final_kernel<<<nodeBlocks, TB>>>(b2, out, N);
}

// round 5
// speedup vs baseline: 1.0647x; 1.0647x over previous
#include <cuda_runtime.h>
#include <cuda_bf16.h>

// Scratch (alloc-free rule: __device__ globals; zero-initialized at load).
// N = 100000 <= MAXN.
// Zeroing is rotated: each array is re-zeroed later in the SAME call, after
// its consumer has read it, so no separate init kernel is ever needed:
//   g_deg : atomics in deg_kernel -> read by prep -> zeroed in s_kernel
//   g_S   : atomics in s_kernel   -> read by t    -> zeroed in out_kernel
//   g_acc : atomics in out_kernel -> read by final-> zeroed in deg_kernel (next call ordering)
#define MAXN (1 << 17)
__device__ float g_deg[MAXN];
__device__ float g_dinv[MAXN];
__device__ float g_a[MAXN];    // dinv[i]*x[i]   (layer-1 source values)
__device__ float g_S[MAXN];    // unnormalized layer-1 aggregate
__device__ float g_u[MAXN];    // dinv[i]*t[i]   (layer-2 source values)
__device__ float g_acc[MAXN];  // unnormalized layer-2 aggregate

#define EPT 8   // edges per thread in edge kernels (R3 sweet spot)

// ---------------------------------------------------------------------------
// Node kernels (tiny, O(N))
// ---------------------------------------------------------------------------

// dinv[i] = 1/sqrt(deg[i]+1)  (+1 = self loop; g_deg counts real edges only)
// a[i] = dinv[i]*x[i]
__global__ void prep_kernel(const float* __restrict__ x, int n) {
    int i = blockIdx.x * blockDim.x + threadIdx.x;
    if (i < n) {
        float di = 1.0f / sqrtf(g_deg[i] + 1.0f);
        g_dinv[i] = di;
        g_a[i]    = di * __ldg(&x[i]);
    }
}

// s = dinv[i]*(S'[i] + a[i])  (the +a[i] is the self-loop edge)
// t[i] = sum_k relu(W1[k]*s + b1[k]) * W2[k];  u[i] = dinv[i]*t[i]
__global__ void t_kernel(const float* __restrict__ W1,
                         const float* __restrict__ b1,
                         const float* __restrict__ W2,
                         int n, int H) {
    int i = blockIdx.x * blockDim.x + threadIdx.x;
    if (i < n) {
        float di = g_dinv[i];
        float s  = di * (g_S[i] + g_a[i]);
        float acc = 0.0f;
        #pragma unroll 16
        for (int k = 0; k < H; k++) {
            float h = fmaf(__ldg(&W1[k]), s, __ldg(&b1[k]));
            h = fmaxf(h, 0.0f);
            acc = fmaf(h, __ldg(&W2[k]), acc);
        }
        g_u[i] = di * acc;
    }
}

// out[i] = dinv[i]*(acc[i] + u[i]) + b2   (the +u[i] is the self-loop edge)
__global__ void final_kernel(const float* __restrict__ b2,
                             float* __restrict__ out, int n) {
    int i = blockIdx.x * blockDim.x + threadIdx.x;
    if (i < n) {
        out[i] = g_dinv[i] * (g_acc[i] + g_u[i]) + __ldg(&b2[0]);
    }
}

// ---------------------------------------------------------------------------
// Edge kernels (int32 indices; EPT edges/thread via int4 loads).
// Per edge: at most 1 scattered gather + 1 scattered RED on L2-resident
// node arrays — the irreducible sector traffic for random indices.
// ---------------------------------------------------------------------------

// deg[col] += 1.  Also zeroes g_acc (its consumer, final_kernel, ran last call;
// out_kernel's atomics on it come later in THIS call).
__global__ void __launch_bounds__(256, 8)
deg_kernel(const int* __restrict__ col, int E, int N) {
    int i = blockIdx.x * blockDim.x + threadIdx.x;
    if (i < N) g_acc[i] = 0.0f;

    int e = i * EPT;
    if (e + EPT - 1 < E) {
        int idx[EPT];
        #pragma unroll
        for (int v = 0; v < EPT / 4; v++) {
            int4 c = *reinterpret_cast<const int4*>(col + e + v * 4);
            idx[v * 4 + 0] = c.x; idx[v * 4 + 1] = c.y;
            idx[v * 4 + 2] = c.z; idx[v * 4 + 3] = c.w;
        }
        #pragma unroll
        for (int v = 0; v < EPT; v++) atomicAdd(&g_deg[idx[v]], 1.0f);
    } else {
        for (; e < E; e++) atomicAdd(&g_deg[col[e]], 1.0f);
    }
}

// S'[col] += a[row].  Also zeroes g_deg (already consumed by prep_kernel).
__global__ void __launch_bounds__(256, 8)
s_kernel(const int* __restrict__ row, const int* __restrict__ col,
         int E, int N) {
    int i = blockIdx.x * blockDim.x + threadIdx.x;
    if (i < N) g_deg[i] = 0.0f;

    int e = i * EPT;
    if (e + EPT - 1 < E) {
        int rs[EPT], cs[EPT];
        #pragma unroll
        for (int v = 0; v < EPT / 4; v++) {
            int4 r = *reinterpret_cast<const int4*>(row + e + v * 4);
            int4 c = *reinterpret_cast<const int4*>(col + e + v * 4);
            rs[v * 4 + 0] = r.x; rs[v * 4 + 1] = r.y;
            rs[v * 4 + 2] = r.z; rs[v * 4 + 3] = r.w;
            cs[v * 4 + 0] = c.x; cs[v * 4 + 1] = c.y;
            cs[v * 4 + 2] = c.z; cs[v * 4 + 3] = c.w;
        }
        float vals[EPT];
        #pragma unroll
        for (int v = 0; v < EPT; v++) vals[v] = __ldg(&g_a[rs[v]]);
        #pragma unroll
        for (int v = 0; v < EPT; v++) atomicAdd(&g_S[cs[v]], vals[v]);
    } else {
        for (; e < E; e++) atomicAdd(&g_S[col[e]], g_a[row[e]]);
    }
}

// acc[col] += u[row].  Also zeroes g_S (already consumed by t_kernel).
__global__ void __launch_bounds__(256, 8)
out_kernel(const int* __restrict__ row, const int* __restrict__ col,
           int E, int N) {
    int i = blockIdx.x * blockDim.x + threadIdx.x;
    if (i < N) g_S[i] = 0.0f;

    int e = i * EPT;
    if (e + EPT - 1 < E) {
        int rs[EPT], cs[EPT];
        #pragma unroll
        for (int v = 0; v < EPT / 4; v++) {
            int4 r = *reinterpret_cast<const int4*>(row + e + v * 4);
            int4 c = *reinterpret_cast<const int4*>(col + e + v * 4);
            rs[v * 4 + 0] = r.x; rs[v * 4 + 1] = r.y;
            rs[v * 4 + 2] = r.z; rs[v * 4 + 3] = r.w;
            cs[v * 4 + 0] = c.x; cs[v * 4 + 1] = c.y;
            cs[v * 4 + 2] = c.z; cs[v * 4 + 3] = c.w;
        }
        float vals[EPT];
        #pragma unroll
        for (int v = 0; v < EPT; v++) vals[v] = __ldg(&g_u[rs[v]]);
        #pragma unroll
        for (int v = 0; v < EPT; v++) atomicAdd(&g_acc[cs[v]], vals[v]);
    } else {
        for (; e < E; e++) atomicAdd(&g_acc[col[e]], g_u[row[e]]);
    }
}

// ---------------------------------------------------------------------------
// Launch
// ---------------------------------------------------------------------------

extern "C" void kernel_launch(void* const* d_in, const int* in_sizes, int n_in,
                              void* d_out, int out_size) {
    const float* x    = (const float*)d_in[0];
    const int*   eidx = (const int*)d_in[1];    // [2, E] int32
    const float* W1   = (const float*)d_in[2];
    const float* b1   = (const float*)d_in[3];
    const float* W2   = (const float*)d_in[4];
    const float* b2   = (const float*)d_in[5];
    float*       out  = (float*)d_out;

    int N = in_sizes[0];
    int E = in_sizes[1] / 2;
    int H = in_sizes[3];

    const int* row = eidx;
    const int* col = eidx + E;

    const int TB = 256;
    int nodeBlocks = (N + TB - 1) / TB;
    int edgeThreads = (E + EPT - 1) / EPT;
    // edge kernels also touch node range [0, N) for fused zeroing
    int edgeBlocks = (max(edgeThreads, N) + TB - 1) / TB;

    deg_kernel<<<edgeBlocks, TB>>>(col, E, N);
    prep_kernel<<<nodeBlocks, TB>>>(x, N);
    s_kernel<<<edgeBlocks, TB>>>(row, col, E, N);
    t_kernel<<<nodeBlocks, TB>>>(W1, b1, W2, N, H);
    out_kernel<<<edgeBlocks, TB>>>(row, col, E, N);
    final_kernel<<<nodeBlocks, TB>>>(b2, out, N);
}

// round 6
// speedup vs baseline: 1.1733x; 1.1020x over previous
#include <cuda_runtime.h>
#include <cuda_fp16.h>

// Scratch (__device__ globals; zero-init at load). N = 100000 <= MAXN.
// Rotated zeroing: each accumulator is re-zeroed by a later kernel in the
// same call, after its consumer has read it:
//   g_deg : atomics in deg_kernel -> read by prep  -> zeroed in s_kernel
//   g_S   : atomics in s_kernel   -> read by t     -> zeroed in out_kernel
//   g_acc : atomics in out_kernel -> read by final -> zeroed in deg_kernel
#define MAXN (1 << 17)
__device__ __align__(16) float  g_deg[MAXN];
__device__ __align__(16) float  g_dinv[MAXN];
__device__ __align__(16) __half g_a[MAXN];    // dinv[i]*x[i]  (fp16: 200KB -> L1-resident gathers)
__device__ __align__(16) float  g_S[MAXN];    // unnormalized layer-1 aggregate (fp32 atomics)
__device__ __align__(16) __half g_u[MAXN];    // dinv[i]*t[i]  (fp16 gathers)
__device__ __align__(16) float  g_acc[MAXN];  // unnormalized layer-2 aggregate

#define EPT 8   // edges per thread in edge kernels

// ---------------------------------------------------------------------------
// Node kernels (O(N), 4 nodes/thread, vectorized)
// ---------------------------------------------------------------------------

// dinv[i] = 1/sqrt(deg[i]+1)  (+1 = self loop; g_deg counts real edges only)
// a[i] = dinv[i]*x[i]  (stored fp16)
__global__ void prep_kernel(const float* __restrict__ x, int n) {
    int i4 = (blockIdx.x * blockDim.x + threadIdx.x) * 4;
    if (i4 + 3 < n) {
        float4 xv = *reinterpret_cast<const float4*>(x + i4);
        float4 dv = *reinterpret_cast<const float4*>(g_deg + i4);
        float4 di;
        di.x = 1.0f / sqrtf(dv.x + 1.0f);
        di.y = 1.0f / sqrtf(dv.y + 1.0f);
        di.z = 1.0f / sqrtf(dv.z + 1.0f);
        di.w = 1.0f / sqrtf(dv.w + 1.0f);
        *reinterpret_cast<float4*>(g_dinv + i4) = di;
        __half2 a01 = __floats2half2_rn(di.x * xv.x, di.y * xv.y);
        __half2 a23 = __floats2half2_rn(di.z * xv.z, di.w * xv.w);
        *reinterpret_cast<__half2*>(g_a + i4)     = a01;
        *reinterpret_cast<__half2*>(g_a + i4 + 2) = a23;
    } else {
        for (int i = i4; i < n; i++) {
            float di = 1.0f / sqrtf(g_deg[i] + 1.0f);
            g_dinv[i] = di;
            g_a[i] = __float2half_rn(di * x[i]);
        }
    }
}

__device__ __forceinline__ float mlp1(float s, const float* W1, const float* b1,
                                      const float* W2, int H) {
    float acc = 0.0f;
    #pragma unroll 16
    for (int k = 0; k < H; k++) {
        float h = fmaf(__ldg(&W1[k]), s, __ldg(&b1[k]));
        h = fmaxf(h, 0.0f);
        acc = fmaf(h, __ldg(&W2[k]), acc);
    }
    return acc;
}

// s = dinv[i]*(S'[i] + a[i]); t = MLP(s); u[i] = dinv[i]*t  (fp16)
__global__ void t_kernel(const float* __restrict__ W1,
                         const float* __restrict__ b1,
                         const float* __restrict__ W2,
                         int n, int H) {
    int i4 = (blockIdx.x * blockDim.x + threadIdx.x) * 4;
    if (i4 + 3 < n) {
        float4 di = *reinterpret_cast<const float4*>(g_dinv + i4);
        float4 Sv = *reinterpret_cast<const float4*>(g_S + i4);
        __half2 a01 = *reinterpret_cast<const __half2*>(g_a + i4);
        __half2 a23 = *reinterpret_cast<const __half2*>(g_a + i4 + 2);
        float2 a0 = __half22float2(a01), a1 = __half22float2(a23);
        float t0 = mlp1(di.x * (Sv.x + a0.x), W1, b1, W2, H);
        float t1 = mlp1(di.y * (Sv.y + a0.y), W1, b1, W2, H);
        float t2 = mlp1(di.z * (Sv.z + a1.x), W1, b1, W2, H);
        float t3 = mlp1(di.w * (Sv.w + a1.y), W1, b1, W2, H);
        *reinterpret_cast<__half2*>(g_u + i4)     = __floats2half2_rn(di.x * t0, di.y * t1);
        *reinterpret_cast<__half2*>(g_u + i4 + 2) = __floats2half2_rn(di.z * t2, di.w * t3);
    } else {
        for (int i = i4; i < n; i++) {
            float di = g_dinv[i];
            float s  = di * (g_S[i] + __half2float(g_a[i]));
            g_u[i] = __float2half_rn(di * mlp1(s, W1, b1, W2, H));
        }
    }
}

// out[i] = dinv[i]*(acc[i] + u[i]) + b2
__global__ void final_kernel(const float* __restrict__ b2,
                             float* __restrict__ out, int n) {
    int i4 = (blockIdx.x * blockDim.x + threadIdx.x) * 4;
    float bb = __ldg(&b2[0]);
    if (i4 + 3 < n) {
        float4 di = *reinterpret_cast<const float4*>(g_dinv + i4);
        float4 av = *reinterpret_cast<const float4*>(g_acc + i4);
        __half2 u01 = *reinterpret_cast<const __half2*>(g_u + i4);
        __half2 u23 = *reinterpret_cast<const __half2*>(g_u + i4 + 2);
        float2 u0 = __half22float2(u01), u1 = __half22float2(u23);
        float4 o;
        o.x = di.x * (av.x + u0.x) + bb;
        o.y = di.y * (av.y + u0.y) + bb;
        o.z = di.z * (av.z + u1.x) + bb;
        o.w = di.w * (av.w + u1.y) + bb;
        *reinterpret_cast<float4*>(out + i4) = o;
    } else {
        for (int i = i4; i < n; i++)
            out[i] = g_dinv[i] * (g_acc[i] + __half2float(g_u[i])) + bb;
    }
}

// ---------------------------------------------------------------------------
// Edge kernels (int32 indices; EPT edges/thread via int4 loads)
// ---------------------------------------------------------------------------

// deg[col] += 1.  Also zeroes g_acc (consumed last call; out_kernel's atomics
// on it come later in THIS call).
__global__ void __launch_bounds__(256, 8)
deg_kernel(const int* __restrict__ col, int E, int N) {
    int i = blockIdx.x * blockDim.x + threadIdx.x;
    if (i < N) g_acc[i] = 0.0f;

    int e = i * EPT;
    if (e + EPT - 1 < E) {
        int idx[EPT];
        #pragma unroll
        for (int v = 0; v < EPT / 4; v++) {
            int4 c = *reinterpret_cast<const int4*>(col + e + v * 4);
            idx[v * 4 + 0] = c.x; idx[v * 4 + 1] = c.y;
            idx[v * 4 + 2] = c.z; idx[v * 4 + 3] = c.w;
        }
        #pragma unroll
        for (int v = 0; v < EPT; v++) atomicAdd(&g_deg[idx[v]], 1.0f);
    } else {
        for (; e < E; e++) atomicAdd(&g_deg[col[e]], 1.0f);
    }
}

// S'[col] += a[row].  Also zeroes g_deg (already consumed by prep_kernel).
__global__ void __launch_bounds__(256, 8)
s_kernel(const int* __restrict__ row, const int* __restrict__ col,
         int E, int N) {
    int i = blockIdx.x * blockDim.x + threadIdx.x;
    if (i < N) g_deg[i] = 0.0f;

    int e = i * EPT;
    if (e + EPT - 1 < E) {
        int rs[EPT], cs[EPT];
        #pragma unroll
        for (int v = 0; v < EPT / 4; v++) {
            int4 r = *reinterpret_cast<const int4*>(row + e + v * 4);
            int4 c = *reinterpret_cast<const int4*>(col + e + v * 4);
            rs[v * 4 + 0] = r.x; rs[v * 4 + 1] = r.y;
            rs[v * 4 + 2] = r.z; rs[v * 4 + 3] = r.w;
            cs[v * 4 + 0] = c.x; cs[v * 4 + 1] = c.y;
            cs[v * 4 + 2] = c.z; cs[v * 4 + 3] = c.w;
        }
        float vals[EPT];
        #pragma unroll
        for (int v = 0; v < EPT; v++) vals[v] = __half2float(__ldg(&g_a[rs[v]]));
        #pragma unroll
        for (int v = 0; v < EPT; v++) atomicAdd(&g_S[cs[v]], vals[v]);
    } else {
        for (; e < E; e++) atomicAdd(&g_S[col[e]], __half2float(g_a[row[e]]));
    }
}

// acc[col] += u[row].  Also zeroes g_S (already consumed by t_kernel).
__global__ void __launch_bounds__(256, 8)
out_kernel(const int* __restrict__ row, const int* __restrict__ col,
           int E, int N) {
    int i = blockIdx.x * blockDim.x + threadIdx.x;
    if (i < N) g_S[i] = 0.0f;

    int e = i * EPT;
    if (e + EPT - 1 < E) {
        int rs[EPT], cs[EPT];
        #pragma unroll
        for (int v = 0; v < EPT / 4; v++) {
            int4 r = *reinterpret_cast<const int4*>(row + e + v * 4);
            int4 c = *reinterpret_cast<const int4*>(col + e + v * 4);
            rs[v * 4 + 0] = r.x; rs[v * 4 + 1] = r.y;
            rs[v * 4 + 2] = r.z; rs[v * 4 + 3] = r.w;
            cs[v * 4 + 0] = c.x; cs[v * 4 + 1] = c.y;
            cs[v * 4 + 2] = c.z; cs[v * 4 + 3] = c.w;
        }
        float vals[EPT];
        #pragma unroll
        for (int v = 0; v < EPT; v++) vals[v] = __half2float(__ldg(&g_u[rs[v]]));
        #pragma unroll
        for (int v = 0; v < EPT; v++) atomicAdd(&g_acc[cs[v]], vals[v]);
    } else {
        for (; e < E; e++) atomicAdd(&g_acc[col[e]], __half2float(g_u[row[e]]));
    }
}

// ---------------------------------------------------------------------------
// Launch
// ---------------------------------------------------------------------------

extern "C" void kernel_launch(void* const* d_in, const int* in_sizes, int n_in,
                              void* d_out, int out_size) {
    const float* x    = (const float*)d_in[0];
    const int*   eidx = (const int*)d_in[1];    // [2, E] int32
    const float* W1   = (const float*)d_in[2];
    const float* b1   = (const float*)d_in[3];
    const float* W2   = (const float*)d_in[4];
    const float* b2   = (const float*)d_in[5];
    float*       out  = (float*)d_out;

    int N = in_sizes[0];
    int E = in_sizes[1] / 2;
    int H = in_sizes[3];

    const int* row = eidx;
    const int* col = eidx + E;

    const int TB = 256;
    int node4Blocks = ((N + 3) / 4 + TB - 1) / TB;
    int edgeThreads = (E + EPT - 1) / EPT;
    int edgeBlocks = (max(edgeThreads, N) + TB - 1) / TB;  // edge kernels also zero [0,N)

    deg_kernel<<<edgeBlocks, TB>>>(col, E, N);
    prep_kernel<<<node4Blocks, TB>>>(x, N);
    s_kernel<<<edgeBlocks, TB>>>(row, col, E, N);
    t_kernel<<<node4Blocks, TB>>>(W1, b1, W2, N, H);
    out_kernel<<<edgeBlocks, TB>>>(row, col, E, N);
    final_kernel<<<node4Blocks, TB>>>(b2, out, N);
}

// round 8
// speedup vs baseline: 1.1859x; 1.0107x over previous
#include <cuda_runtime.h>
#include <cuda_fp16.h>

// Scratch (__device__ globals; zero-init at load). N = 100000 <= MAXN.
// Rotated zeroing: each accumulator is re-zeroed by a later kernel in the
// same call, after its consumer has read it:
//   g_deg : atomics in deg_kernel -> read by prep  -> zeroed in scatter pass 1
//   g_S   : atomics in pass 1     -> read by t     -> zeroed in scatter pass 2
//   g_acc : atomics in pass 2     -> read by final -> zeroed in deg_kernel
#define MAXN (1 << 17)
__device__ __align__(16) float  g_deg[MAXN];
__device__ __align__(16) float  g_dinv[MAXN];
__device__ __align__(16) __half g_a[MAXN];    // dinv[i]*x[i]  (fp16, 200KB: fits smem)
__device__ __align__(16) float  g_S[MAXN];    // layer-1 aggregate (fp32 REDs)
__device__ __align__(16) __half g_u[MAXN];    // dinv[i]*t[i]  (fp16, 200KB: fits smem)
__device__ __align__(16) float  g_acc[MAXN];  // layer-2 aggregate

#define EPT 8                  // edges/thread for deg_kernel
#define SBLOCKS 148            // one scatter block per SM (single wave)
#define STHREADS 1024

// ---------------------------------------------------------------------------
// Node kernels
// ---------------------------------------------------------------------------

// dinv[i] = 1/sqrt(deg[i]+1)  (+1 = self loop); a[i] = dinv[i]*x[i] (fp16)
__global__ void prep_kernel(const float* __restrict__ x, int n) {
    int i4 = (blockIdx.x * blockDim.x + threadIdx.x) * 4;
    if (i4 + 3 < n) {
        float4 xv = *reinterpret_cast<const float4*>(x + i4);
        float4 dv = *reinterpret_cast<const float4*>(g_deg + i4);
        float4 di;
        di.x = 1.0f / sqrtf(dv.x + 1.0f);
        di.y = 1.0f / sqrtf(dv.y + 1.0f);
        di.z = 1.0f / sqrtf(dv.z + 1.0f);
        di.w = 1.0f / sqrtf(dv.w + 1.0f);
        *reinterpret_cast<float4*>(g_dinv + i4) = di;
        *reinterpret_cast<__half2*>(g_a + i4)     = __floats2half2_rn(di.x * xv.x, di.y * xv.y);
        *reinterpret_cast<__half2*>(g_a + i4 + 2) = __floats2half2_rn(di.z * xv.z, di.w * xv.w);
    } else {
        for (int i = i4; i < n; i++) {
            float di = 1.0f / sqrtf(g_deg[i] + 1.0f);
            g_dinv[i] = di;
            g_a[i] = __float2half_rn(di * x[i]);
        }
    }
}

// s = dinv*(S'+a); t = MLP(s); u = dinv*t  (fp16)
__global__ void t_kernel(const float* __restrict__ W1,
                         const float* __restrict__ b1,
                         const float* __restrict__ W2,
                         int n, int H) {
    int i = blockIdx.x * blockDim.x + threadIdx.x;
    if (i < n) {
        float di = g_dinv[i];
        float s  = di * (g_S[i] + __half2float(g_a[i]));
        float acc = 0.0f;
        #pragma unroll 16
        for (int k = 0; k < H; k++) {
            float h = fmaf(__ldg(&W1[k]), s, __ldg(&b1[k]));
            h = fmaxf(h, 0.0f);
            acc = fmaf(h, __ldg(&W2[k]), acc);
        }
        g_u[i] = __float2half_rn(di * acc);
    }
}

// out[i] = dinv[i]*(acc[i] + u[i]) + b2
__global__ void final_kernel(const float* __restrict__ b2,
                             float* __restrict__ out, int n) {
    int i = blockIdx.x * blockDim.x + threadIdx.x;
    if (i < n) {
        out[i] = g_dinv[i] * (g_acc[i] + __half2float(g_u[i])) + __ldg(&b2[0]);
    }
}

// ---------------------------------------------------------------------------
// Edge kernels
// ---------------------------------------------------------------------------

// deg[col] += 1 (REDG floor). Also zeroes g_acc.
__global__ void __launch_bounds__(256, 8)
deg_kernel(const int* __restrict__ col, int E, int N) {
    int i = blockIdx.x * blockDim.x + threadIdx.x;
    if (i < N) g_acc[i] = 0.0f;

    int e = i * EPT;
    if (e + EPT - 1 < E) {
        int idx[EPT];
        #pragma unroll
        for (int v = 0; v < EPT / 4; v++) {
            int4 c = *reinterpret_cast<const int4*>(col + e + v * 4);
            idx[v * 4 + 0] = c.x; idx[v * 4 + 1] = c.y;
            idx[v * 4 + 2] = c.z; idx[v * 4 + 3] = c.w;
        }
        #pragma unroll
        for (int v = 0; v < EPT; v++) atomicAdd(&g_deg[idx[v]], 1.0f);
    } else {
        for (; e < E; e++) atomicAdd(&g_deg[col[e]], 1.0f);
    }
}

// Scatter pass: dst[col] += table[row], table cached in smem (random LDS gather,
// scattered REDG only). PASS=0: g_a -> g_S (zeroes g_deg).
//                       PASS=1: g_u -> g_acc (zeroes g_S).
// Tables/dsts are selected INSIDE device code (never pass __device__ globals
// as kernel args from host — that was the R7 bug).
template <int PASS>
__global__ void __launch_bounds__(STHREADS, 1)
scatter_kernel(const int* __restrict__ row, const int* __restrict__ col,
               int E, int N) {
    extern __shared__ __half sh[];   // N halves (200KB for N=100K)

    const __half* table = (PASS == 0) ? g_a : g_u;
    float* dst          = (PASS == 0) ? g_S : g_acc;

    int tid = blockIdx.x * blockDim.x + threadIdx.x;
    int nthreads = gridDim.x * blockDim.x;

    // fused zeroing of the already-consumed accumulator
    if (tid < N) {
        if (PASS == 0) g_deg[tid] = 0.0f;
        else           g_S[tid]   = 0.0f;
    }

    // cooperative copy of the gather table into smem (int4-coalesced;
    // over-read past N stays within MAXN -> safe)
    int nvec = (N * 2 + 15) / 16;
    const int4* src4 = reinterpret_cast<const int4*>(table);
    int4* sh4 = reinterpret_cast<int4*>(sh);
    for (int v = threadIdx.x; v < nvec; v += blockDim.x) sh4[v] = src4[v];
    __syncthreads();

    // grid-stride over edge quads
    int E4 = E & ~3;
    int stride = nthreads * 4;
    for (int e = tid * 4; e < E4; e += stride) {
        int4 r = *reinterpret_cast<const int4*>(row + e);
        int4 c = *reinterpret_cast<const int4*>(col + e);
        float v0 = __half2float(sh[r.x]);
        float v1 = __half2float(sh[r.y]);
        float v2 = __half2float(sh[r.z]);
        float v3 = __half2float(sh[r.w]);
        atomicAdd(&dst[c.x], v0);
        atomicAdd(&dst[c.y], v1);
        atomicAdd(&dst[c.z], v2);
        atomicAdd(&dst[c.w], v3);
    }
    // tail (<4 edges)
    if (tid == 0) {
        for (int e = E4; e < E; e++)
            atomicAdd(&dst[col[e]], __half2float(sh[row[e]]));
    }
}

// ---------------------------------------------------------------------------
// Launch
// ---------------------------------------------------------------------------

extern "C" void kernel_launch(void* const* d_in, const int* in_sizes, int n_in,
                              void* d_out, int out_size) {
    const float* x    = (const float*)d_in[0];
    const int*   eidx = (const int*)d_in[1];    // [2, E] int32
    const float* W1   = (const float*)d_in[2];
    const float* b1   = (const float*)d_in[3];
    const float* W2   = (const float*)d_in[4];
    const float* b2   = (const float*)d_in[5];
    float*       out  = (float*)d_out;

    int N = in_sizes[0];
    int E = in_sizes[1] / 2;
    int H = in_sizes[3];

    const int* row = eidx;
    const int* col = eidx + E;

    // Opt in to 200KB+ dynamic smem. Idempotent, not stream-ordered, not an
    // allocation -> capture-safe; called unconditionally (no static guards).
    int shBytes = ((N * 2 + 15) / 16) * 16;
    cudaFuncSetAttribute(scatter_kernel<0>,
                         cudaFuncAttributeMaxDynamicSharedMemorySize, 227 * 1024);
    cudaFuncSetAttribute(scatter_kernel<1>,
                         cudaFuncAttributeMaxDynamicSharedMemorySize, 227 * 1024);

    const int TB = 256;
    int nodeBlocks  = (N + TB - 1) / TB;
    int node4Blocks = ((N + 3) / 4 + TB - 1) / TB;
    int edgeThreads = (E + EPT - 1) / EPT;
    int degBlocks   = (max(edgeThreads, N) + TB - 1) / TB;

    deg_kernel<<<degBlocks, TB>>>(col, E, N);
    prep_kernel<<<node4Blocks, TB>>>(x, N);
    scatter_kernel<0><<<SBLOCKS, STHREADS, shBytes>>>(row, col, E, N);
    t_kernel<<<nodeBlocks, TB>>>(W1, b1, W2, N, H);
    scatter_kernel<1><<<SBLOCKS, STHREADS, shBytes>>>(row, col, E, N);
    final_kernel<<<nodeBlocks, TB>>>(b2, out, N);
}